// round 3
// baseline (speedup 1.0000x reference)
#include <cuda_runtime.h>
#include <cstdint>
#include <cmath>

// ---------------------------------------------------------------------------
// Problem constants
// ---------------------------------------------------------------------------
#define TOK   4096          // B*S
#define DM    1024          // d_model
#define DF    4096          // d_ff
#define SEQ   2048
#define BATCH 2
#define NH    16
#define DK    64
#define LN_EPS 1e-6f

// ---------------------------------------------------------------------------
// Scratch (device globals: allocation-free rule)
// ---------------------------------------------------------------------------
__device__ float g_q   [TOK * DM];
__device__ float g_k   [TOK * DM];
__device__ float g_v   [TOK * DM];
__device__ float g_attn[TOK * DM];
__device__ float g_proj[TOK * DM];
__device__ float g_h   [TOK * DM];
__device__ float g_f1  [TOK * DF];
__device__ float g_f2  [TOK * DM];

// ---------------------------------------------------------------------------
// PTX helpers
// ---------------------------------------------------------------------------
__device__ __forceinline__ void cp_async16(void* smem_dst, const void* gmem_src) {
    uint32_t s = (uint32_t)__cvta_generic_to_shared(smem_dst);
    asm volatile("cp.async.cg.shared.global [%0], [%1], 16;\n" :: "r"(s), "l"(gmem_src));
}
__device__ __forceinline__ void cp_commit() {
    asm volatile("cp.async.commit_group;\n" ::: "memory");
}
__device__ __forceinline__ uint32_t f2tf32(float x) {
    uint32_t r;
    asm("cvt.rna.tf32.f32 %0, %1;\n" : "=r"(r) : "f"(x));
    return r;
}
__device__ __forceinline__ void mma8(float* c, const uint32_t* a, const uint32_t* b) {
    asm volatile(
        "mma.sync.aligned.m16n8k8.row.col.f32.tf32.tf32.f32 "
        "{%0,%1,%2,%3},{%4,%5,%6,%7},{%8,%9},{%0,%1,%2,%3};\n"
        : "+f"(c[0]), "+f"(c[1]), "+f"(c[2]), "+f"(c[3])
        : "r"(a[0]), "r"(a[1]), "r"(a[2]), "r"(a[3]), "r"(b[0]), "r"(b[1]));
}

// ---------------------------------------------------------------------------
// GEMM core: C[M,N] = A[M,K] @ B[K,N] + bias  (optional ReLU)
// tiles: 128x128x32, 256 threads (8 warps as 2m x 4n, each 64x32),
// tf32 mma.sync m16n8k8, cp.async double-buffered smem.
// smem padding: A row stride 36 floats, B row stride 136 floats.
// All dims are multiples of the tile sizes; no bounds checks.
// ---------------------------------------------------------------------------
#define GEMM_SMEM ((2*128*36 + 2*32*136) * 4)

template<bool RELU>
__device__ __forceinline__ void gemm_tile(
    const float* __restrict__ A, const float* __restrict__ B,
    const float* __restrict__ bias, float* __restrict__ C,
    int N, int K, int bm, int bn)
{
    extern __shared__ float smf[];
    float* sA = smf;               // [2][128][36]
    float* sB = smf + 2*128*36;    // [2][32][136]

    const int tid  = threadIdx.x;
    const int lane = tid & 31;
    const int warp = tid >> 5;
    const int g    = lane >> 2;
    const int t4   = lane & 3;
    const int wm   = (warp & 1) * 64;
    const int wn   = (warp >> 1) * 32;

    float acc[4][4][4];
#pragma unroll
    for (int mt = 0; mt < 4; mt++)
#pragma unroll
        for (int nt = 0; nt < 4; nt++)
#pragma unroll
            for (int i = 0; i < 4; i++) acc[mt][nt][i] = 0.f;

    auto load_tile = [&](int kt, int buf) {
        float* dA = sA + buf * (128 * 36);
        float* dB = sB + buf * (32 * 136);
#pragma unroll
        for (int j = 0; j < 4; j++) {
            int t = tid + 256 * j;
            int r = t >> 3, c = (t & 7) * 4;
            cp_async16(dA + r * 36 + c, A + (size_t)(bm + r) * K + kt + c);
        }
#pragma unroll
        for (int j = 0; j < 4; j++) {
            int t = tid + 256 * j;
            int r = t >> 5, c = (t & 31) * 4;
            cp_async16(dB + r * 136 + c, B + (size_t)(kt + r) * N + bn + c);
        }
        cp_commit();
    };

    load_tile(0, 0);
    const int nk = K >> 5;

    for (int kt = 0; kt < nk; kt++) {
        const int buf = kt & 1;
        if (kt + 1 < nk) {
            load_tile((kt + 1) << 5, buf ^ 1);
            asm volatile("cp.async.wait_group 1;\n" ::: "memory");
        } else {
            asm volatile("cp.async.wait_group 0;\n" ::: "memory");
        }
        __syncthreads();

        const float* pA = sA + buf * (128 * 36);
        const float* pB = sB + buf * (32 * 136);
#pragma unroll
        for (int kk = 0; kk < 4; kk++) {
            uint32_t af[4][4], bf[4][2];
#pragma unroll
            for (int mt = 0; mt < 4; mt++) {
                const float* p = pA + (wm + mt * 16 + g) * 36 + kk * 8;
                af[mt][0] = f2tf32(p[t4]);
                af[mt][1] = f2tf32(p[8 * 36 + t4]);
                af[mt][2] = f2tf32(p[t4 + 4]);
                af[mt][3] = f2tf32(p[8 * 36 + t4 + 4]);
            }
#pragma unroll
            for (int nt = 0; nt < 4; nt++) {
                const float* p = pB + (kk * 8 + t4) * 136 + wn + nt * 8 + g;
                bf[nt][0] = f2tf32(p[0]);
                bf[nt][1] = f2tf32(p[4 * 136]);
            }
#pragma unroll
            for (int mt = 0; mt < 4; mt++)
#pragma unroll
                for (int nt = 0; nt < 4; nt++)
                    mma8(acc[mt][nt], af[mt], bf[nt]);
        }
        __syncthreads();
    }

#pragma unroll
    for (int mt = 0; mt < 4; mt++) {
#pragma unroll
        for (int nt = 0; nt < 4; nt++) {
            int row = bm + wm + mt * 16 + g;
            int col = bn + wn + nt * 8 + 2 * t4;
            float bb0 = bias[col], bb1 = bias[col + 1];
            float v0 = acc[mt][nt][0] + bb0;
            float v1 = acc[mt][nt][1] + bb1;
            float v2 = acc[mt][nt][2] + bb0;
            float v3 = acc[mt][nt][3] + bb1;
            if (RELU) {
                v0 = fmaxf(v0, 0.f); v1 = fmaxf(v1, 0.f);
                v2 = fmaxf(v2, 0.f); v3 = fmaxf(v3, 0.f);
            }
            *(float2*)(C + (size_t)row * N + col)       = make_float2(v0, v1);
            *(float2*)(C + (size_t)(row + 8) * N + col) = make_float2(v2, v3);
        }
    }
}

template<bool RELU>
__global__ void __launch_bounds__(256)
gemm_tf32_kernel(const float* __restrict__ A, const float* __restrict__ B,
                 const float* __restrict__ bias, float* __restrict__ C,
                 int N, int K)
{
    gemm_tile<RELU>(A, B, bias, C, N, K, blockIdx.y * 128, blockIdx.x * 128);
}

// Fused QKV: one launch, blockIdx.z in {0,1,2} selects {Wq,Wk,Wv}.
// Packs 768 CTAs into one grid: fewer wave-quantization tails, and the
// three streams share A=x in L2.
__global__ void __launch_bounds__(256)
gemm_qkv_kernel(const float* __restrict__ x,
                const float* __restrict__ Wq, const float* __restrict__ bq, float* __restrict__ q,
                const float* __restrict__ Wk, const float* __restrict__ bk, float* __restrict__ k,
                const float* __restrict__ Wv, const float* __restrict__ bv, float* __restrict__ v)
{
    const float* W; const float* bb; float* out;
    if (blockIdx.z == 0)      { W = Wq; bb = bq; out = q; }
    else if (blockIdx.z == 1) { W = Wk; bb = bk; out = k; }
    else                      { W = Wv; bb = bv; out = v; }
    gemm_tile<false>(x, W, bb, out, DM, DM, blockIdx.y * 128, blockIdx.x * 128);
}

// ---------------------------------------------------------------------------
// Flash attention: per block one (b, h, m-tile of 64 rows).
// Q tile [64,64] (pre-scaled by 1/8) in smem; 32 KV tiles of 64 rows,
// double-buffered cp.async. Online softmax; P staged via warp-private smem.
// ---------------------------------------------------------------------------
#define ATTN_SMEM ((64*68 + 2*64*68 + 2*64*72 + 64*68) * 4)

__global__ void __launch_bounds__(128)
attn_kernel(const float* __restrict__ Q, const float* __restrict__ Km,
            const float* __restrict__ Vm, float* __restrict__ O)
{
    extern __shared__ float smf[];
    float* sQ = smf;                      // 64*68
    float* sK = smf + 4352;               // 2 * 64*68
    float* sV = smf + 4352 + 8704;        // 2 * 64*72
    float* sP = smf + 4352 + 8704 + 9216; // 64*68

    const int tid  = threadIdx.x;
    const int warp = tid >> 5;
    const int lane = tid & 31;
    const int g    = lane >> 2;
    const int t4   = lane & 3;
    const int b    = blockIdx.y >> 4;
    const int h    = blockIdx.y & 15;
    const int s0   = blockIdx.x * 64;
    const size_t hoff = (size_t)h * DK;

    const float* qg = Q + ((size_t)(b * SEQ + s0)) * DM + hoff;
#pragma unroll
    for (int j = 0; j < 8; j++) {
        int t = tid + 128 * j;
        int r = t >> 4, c = (t & 15) * 4;
        float4 val = *(const float4*)(qg + (size_t)r * DM + c);
        val.x *= 0.125f; val.y *= 0.125f; val.z *= 0.125f; val.w *= 0.125f;
        *(float4*)(sQ + r * 68 + c) = val;
    }

    auto load_kv = [&](int it, int buf) {
        const float* kg = Km + ((size_t)(b * SEQ + it * 64)) * DM + hoff;
        const float* vg = Vm + ((size_t)(b * SEQ + it * 64)) * DM + hoff;
        float* dK = sK + buf * 4352;
        float* dV = sV + buf * 4608;
#pragma unroll
        for (int j = 0; j < 8; j++) {
            int t = tid + 128 * j;
            int r = t >> 4, c = (t & 15) * 4;
            cp_async16(dK + r * 68 + c, kg + (size_t)r * DM + c);
            cp_async16(dV + r * 72 + c, vg + (size_t)r * DM + c);
        }
        cp_commit();
    };

    load_kv(0, 0);

    float m0 = -INFINITY, m1 = -INFINITY, l0 = 0.f, l1 = 0.f;
    float o[8][4];
#pragma unroll
    for (int nt = 0; nt < 8; nt++)
#pragma unroll
        for (int i = 0; i < 4; i++) o[nt][i] = 0.f;

    for (int it = 0; it < 32; it++) {
        const int buf = it & 1;
        if (it + 1 < 32) {
            load_kv(it + 1, buf ^ 1);
            asm volatile("cp.async.wait_group 1;\n" ::: "memory");
        } else {
            asm volatile("cp.async.wait_group 0;\n" ::: "memory");
        }
        __syncthreads();

        const float* pK = sK + buf * 4352;
        const float* pV = sV + buf * 4608;

        float s[8][4];
#pragma unroll
        for (int nt = 0; nt < 8; nt++)
#pragma unroll
            for (int i = 0; i < 4; i++) s[nt][i] = 0.f;

#pragma unroll
        for (int kk = 0; kk < 8; kk++) {
            uint32_t a[4];
            const float* ap = sQ + (warp * 16 + g) * 68 + kk * 8;
            a[0] = f2tf32(ap[t4]);
            a[1] = f2tf32(ap[8 * 68 + t4]);
            a[2] = f2tf32(ap[t4 + 4]);
            a[3] = f2tf32(ap[8 * 68 + t4 + 4]);
#pragma unroll
            for (int nt = 0; nt < 8; nt++) {
                uint32_t bfr[2];
                const float* bp = pK + (nt * 8 + g) * 68 + kk * 8 + t4;
                bfr[0] = f2tf32(bp[0]);
                bfr[1] = f2tf32(bp[4]);
                mma8(s[nt], a, bfr);
            }
        }

        float mx0 = -INFINITY, mx1 = -INFINITY;
#pragma unroll
        for (int nt = 0; nt < 8; nt++) {
            mx0 = fmaxf(mx0, fmaxf(s[nt][0], s[nt][1]));
            mx1 = fmaxf(mx1, fmaxf(s[nt][2], s[nt][3]));
        }
        mx0 = fmaxf(mx0, __shfl_xor_sync(0xffffffffu, mx0, 1));
        mx0 = fmaxf(mx0, __shfl_xor_sync(0xffffffffu, mx0, 2));
        mx1 = fmaxf(mx1, __shfl_xor_sync(0xffffffffu, mx1, 1));
        mx1 = fmaxf(mx1, __shfl_xor_sync(0xffffffffu, mx1, 2));
        float mn0 = fmaxf(m0, mx0), mn1 = fmaxf(m1, mx1);
        float al0 = __expf(m0 - mn0), al1 = __expf(m1 - mn1);
        m0 = mn0; m1 = mn1;

        float sum0 = 0.f, sum1 = 0.f;
#pragma unroll
        for (int nt = 0; nt < 8; nt++) {
            s[nt][0] = __expf(s[nt][0] - mn0);
            s[nt][1] = __expf(s[nt][1] - mn0);
            s[nt][2] = __expf(s[nt][2] - mn1);
            s[nt][3] = __expf(s[nt][3] - mn1);
            sum0 += s[nt][0] + s[nt][1];
            sum1 += s[nt][2] + s[nt][3];
        }
        sum0 += __shfl_xor_sync(0xffffffffu, sum0, 1);
        sum0 += __shfl_xor_sync(0xffffffffu, sum0, 2);
        sum1 += __shfl_xor_sync(0xffffffffu, sum1, 1);
        sum1 += __shfl_xor_sync(0xffffffffu, sum1, 2);
        l0 = l0 * al0 + sum0;
        l1 = l1 * al1 + sum1;

#pragma unroll
        for (int nt = 0; nt < 8; nt++) {
            o[nt][0] *= al0; o[nt][1] *= al0;
            o[nt][2] *= al1; o[nt][3] *= al1;
            float* pp = sP + (warp * 16 + g) * 68 + nt * 8 + 2 * t4;
            *(float2*)pp            = make_float2(s[nt][0], s[nt][1]);
            *(float2*)(pp + 8 * 68) = make_float2(s[nt][2], s[nt][3]);
        }
        __syncwarp();

#pragma unroll
        for (int kk = 0; kk < 8; kk++) {
            uint32_t a[4];
            const float* ap = sP + (warp * 16 + g) * 68 + kk * 8;
            a[0] = f2tf32(ap[t4]);
            a[1] = f2tf32(ap[8 * 68 + t4]);
            a[2] = f2tf32(ap[t4 + 4]);
            a[3] = f2tf32(ap[8 * 68 + t4 + 4]);
#pragma unroll
            for (int nt = 0; nt < 8; nt++) {
                uint32_t bfr[2];
                const float* bp = pV + (kk * 8 + t4) * 72 + nt * 8 + g;
                bfr[0] = f2tf32(bp[0]);
                bfr[1] = f2tf32(bp[4 * 72]);
                mma8(o[nt], a, bfr);
            }
        }
        __syncthreads();
    }

    const float i0 = 1.f / l0, i1 = 1.f / l1;
    const int row = s0 + warp * 16 + g;
#pragma unroll
    for (int nt = 0; nt < 8; nt++) {
        int col = h * DK + nt * 8 + 2 * t4;
        float* og = O + ((size_t)(b * SEQ + row)) * DM + col;
        *(float2*)og            = make_float2(o[nt][0] * i0, o[nt][1] * i0);
        *(float2*)(og + 8 * DM) = make_float2(o[nt][2] * i1, o[nt][3] * i1);
    }
}

// ---------------------------------------------------------------------------
// Residual add + custom LayerNorm: out = gamma*((v-mean)/(std+eps)) + beta.
// ---------------------------------------------------------------------------
__global__ void __launch_bounds__(256)
add_ln_kernel(const float* __restrict__ X, const float* __restrict__ Y,
              const float* __restrict__ G, const float* __restrict__ Bt,
              float* __restrict__ Out)
{
    __shared__ float red[8];
    __shared__ float sMean, sInv;
    const int row = blockIdx.x, tid = threadIdx.x;
    const size_t base = (size_t)row * DM + tid * 4;

    float4 xv = *(const float4*)(X + base);
    float4 yv = *(const float4*)(Y + base);
    float4 v = make_float4(xv.x + yv.x, xv.y + yv.y, xv.z + yv.z, xv.w + yv.w);

    float s = v.x + v.y + v.z + v.w;
#pragma unroll
    for (int off = 16; off; off >>= 1) s += __shfl_xor_sync(0xffffffffu, s, off);
    if ((tid & 31) == 0) red[tid >> 5] = s;
    __syncthreads();
    if (tid == 0) {
        float t = 0.f;
#pragma unroll
        for (int i = 0; i < 8; i++) t += red[i];
        sMean = t * (1.0f / DM);
    }
    __syncthreads();
    const float mean = sMean;

    float dx = v.x - mean, dy = v.y - mean, dz = v.z - mean, dw = v.w - mean;
    float q = dx * dx + dy * dy + dz * dz + dw * dw;
#pragma unroll
    for (int off = 16; off; off >>= 1) q += __shfl_xor_sync(0xffffffffu, q, off);
    if ((tid & 31) == 0) red[tid >> 5] = q;
    __syncthreads();
    if (tid == 0) {
        float t = 0.f;
#pragma unroll
        for (int i = 0; i < 8; i++) t += red[i];
        sInv = 1.0f / (sqrtf(t * (1.0f / DM)) + LN_EPS);
    }
    __syncthreads();
    const float inv = sInv;

    float4 gv = *(const float4*)(G + tid * 4);
    float4 bv = *(const float4*)(Bt + tid * 4);
    float4 ov = make_float4(dx * inv * gv.x + bv.x, dy * inv * gv.y + bv.y,
                            dz * inv * gv.z + bv.z, dw * inv * gv.w + bv.w);
    *(float4*)(Out + base) = ov;
}

// ---------------------------------------------------------------------------
// Launch
// ---------------------------------------------------------------------------
extern "C" void kernel_launch(void* const* d_in, const int* in_sizes, int n_in,
                              void* d_out, int out_size)
{
    (void)in_sizes; (void)n_in; (void)out_size;
    const float* x   = (const float*)d_in[0];
    const float* Wq  = (const float*)d_in[1];
    const float* bq  = (const float*)d_in[2];
    const float* Wk  = (const float*)d_in[3];
    const float* bk  = (const float*)d_in[4];
    const float* Wv  = (const float*)d_in[5];
    const float* bv  = (const float*)d_in[6];
    const float* Wo  = (const float*)d_in[7];
    const float* bo  = (const float*)d_in[8];
    const float* W1  = (const float*)d_in[9];
    const float* b1  = (const float*)d_in[10];
    const float* W2  = (const float*)d_in[11];
    const float* b2  = (const float*)d_in[12];
    const float* g1  = (const float*)d_in[13];
    const float* be1 = (const float*)d_in[14];
    const float* g2  = (const float*)d_in[15];
    const float* be2 = (const float*)d_in[16];

    float *q, *k, *v, *attn, *proj, *h, *f1, *f2;
    cudaGetSymbolAddress((void**)&q,    g_q);
    cudaGetSymbolAddress((void**)&k,    g_k);
    cudaGetSymbolAddress((void**)&v,    g_v);
    cudaGetSymbolAddress((void**)&attn, g_attn);
    cudaGetSymbolAddress((void**)&proj, g_proj);
    cudaGetSymbolAddress((void**)&h,    g_h);
    cudaGetSymbolAddress((void**)&f1,   g_f1);
    cudaGetSymbolAddress((void**)&f2,   g_f2);

    cudaFuncSetAttribute(gemm_tf32_kernel<false>,
                         cudaFuncAttributeMaxDynamicSharedMemorySize, GEMM_SMEM);
    cudaFuncSetAttribute(gemm_tf32_kernel<true>,
                         cudaFuncAttributeMaxDynamicSharedMemorySize, GEMM_SMEM);
    cudaFuncSetAttribute(gemm_qkv_kernel,
                         cudaFuncAttributeMaxDynamicSharedMemorySize, GEMM_SMEM);
    cudaFuncSetAttribute(attn_kernel,
                         cudaFuncAttributeMaxDynamicSharedMemorySize, ATTN_SMEM);

    const dim3 gQKV(DM / 128, TOK / 128);

    gemm_qkv_kernel<<<dim3(DM / 128, TOK / 128, 3), 256, GEMM_SMEM>>>(
        x, Wq, bq, q, Wk, bk, k, Wv, bv, v);

    attn_kernel<<<dim3(SEQ / 64, BATCH * NH), 128, ATTN_SMEM>>>(q, k, v, attn);

    gemm_tf32_kernel<false><<<gQKV, 256, GEMM_SMEM>>>(attn, Wo, bo, proj, DM, DM);

    add_ln_kernel<<<TOK, 256>>>(x, proj, g1, be1, h);

    gemm_tf32_kernel<true><<<dim3(DF / 128, TOK / 128), 256, GEMM_SMEM>>>(h, W1, b1, f1, DF, DM);
    gemm_tf32_kernel<false><<<gQKV, 256, GEMM_SMEM>>>(f1, W2, b2, f2, DM, DF);

    add_ln_kernel<<<TOK, 256>>>(h, f2, g2, be2, (float*)d_out);
}